// round 14
// baseline (speedup 1.0000x reference)
#include <cuda_runtime.h>
#include <cstdint>
#include <math.h>

// x [128, 1, 512, 512] fp32.
//   pred = softplus(x); m = max over sample; out = (m > 1e-8) ? pred/m : pred.
// softplus monotone => m = softplus(max(x)).
//
// R14: warp-specialized persistent kernel. Bulk designs are hard-capped at
// 57.6us by the ~7 TB/s LTS limit (402 MB of L2 traffic). SMEM staging cuts
// traffic to 268 MB (39us floor) but R12/R13 serialized load->barrier->spin->
// store per CTA, draining the read pipeline (DRAM 40%). Here producers
// (warps 0-15) stream chunks into a 6-stage SMEM ring and publish per-sample
// maxes WITHOUT ever waiting on the sample dependency; consumers (warps
// 16-31) absorb the dependency spin inside the ring's 6-chunk elasticity.

#define SAMPLES 128
#define SAMPLE_ELEMS (512 * 512)              // 262144
#define CHUNKS 32                             // chunks per sample
#define CHUNK_N4 (SAMPLE_ELEMS / CHUNKS / 4)  // 2048 float4 = 32 KB
#define NSTAGES 6
#define THREADS 1024
#define HALF 512                              // producer / consumer group size
#define GRID 148                              // one CTA per SM
#define TOTAL_WORK (SAMPLES * CHUNKS)         // 4096
#define SMEM_BYTES (NSTAGES * CHUNK_N4 * 16)  // 196608
#define EPS 1e-8f
#define LOG2E 1.4426950408889634f
#define LN2   0.6931471805599453f

__device__ unsigned g_smax[SAMPLES];          // ordered-uint max; 0 = empty
__device__ unsigned g_arrive[SAMPLES];
__device__ unsigned g_leave[SAMPLES];         // self-reset for graph replay

__device__ __forceinline__ unsigned ord_encode(float f) {
    unsigned u = __float_as_uint(f);
    return (u >> 31) ? ~u : (u | 0x80000000u);
}
__device__ __forceinline__ float ord_decode(unsigned u) {
    return __uint_as_float((u >> 31) ? (u ^ 0x80000000u) : ~u);
}
__device__ __forceinline__ float softplus_accurate(float x) {
    return fmaxf(x, 0.0f) + log1pf(__expf(-fabsf(x)));
}
__device__ __forceinline__ float ex2f(float x) {
    float r; asm("ex2.approx.ftz.f32 %0, %1;" : "=f"(r) : "f"(x)); return r;
}
__device__ __forceinline__ float lg2f(float x) {
    float r; asm("lg2.approx.ftz.f32 %0, %1;" : "=f"(r) : "f"(x)); return r;
}
__device__ __forceinline__ float softplus_scaled(float x, float scale, float scale_ln2) {
    float t = ex2f(-LOG2E * fabsf(x));        // e^(-|x|)
    float l = lg2f(1.0f + t);                 // log2(1 + e^-|x|)
    return fmaf(scale, fmaxf(x, 0.0f), scale_ln2 * l);
}
__device__ __forceinline__ unsigned ld_acquire_gpu(const unsigned* p) {
    unsigned v;
    asm volatile("ld.acquire.gpu.u32 %0, [%1];" : "=r"(v) : "l"(p));
    return v;
}
__device__ __forceinline__ int ld_acquire_sh(const int* p) {
    int v;
    asm volatile("ld.acquire.cta.shared.s32 %0, [%1];"
                 : "=r"(v) : "r"((unsigned)__cvta_generic_to_shared(p)));
    return v;
}
__device__ __forceinline__ void st_release_sh(int* p, int v) {
    asm volatile("st.release.cta.shared.s32 [%0], %1;"
                 :: "r"((unsigned)__cvta_generic_to_shared(p)), "r"(v) : "memory");
}

__global__ __launch_bounds__(THREADS, 1)
void ws_kernel(const float* __restrict__ x, float* __restrict__ out) {
    extern __shared__ float4 ring[];              // NSTAGES * 2048 float4
    __shared__ int s_state[NSTAGES];              // 0 = empty, 1 = full
    __shared__ float s_red[NSTAGES][HALF / 32];   // per-stage producer partials
    __shared__ float s_scale[NSTAGES];

    const int tid = threadIdx.x;
    if (tid < NSTAGES) s_state[tid] = 0;
    __syncthreads();                              // single full-CTA sync

    const int bid = blockIdx.x;

    if (tid < HALF) {
        // ================= PRODUCERS (warps 0-15) =================
        const int ptid = tid;
        const int pwid = ptid >> 5;
        int st = 0;
        for (int w = bid; w < TOTAL_WORK; w += GRID) {
            while (ld_acquire_sh(&s_state[st]) != 0) __nanosleep(40);

            const float4* __restrict__ xin =
                reinterpret_cast<const float4*>(x) + (size_t)w * CHUNK_N4;
            float4* buf = ring + st * CHUNK_N4;

            float4 a = __ldcs(&xin[ptid]);
            float4 b = __ldcs(&xin[ptid + HALF]);
            float4 c = __ldcs(&xin[ptid + 2 * HALF]);
            float4 d = __ldcs(&xin[ptid + 3 * HALF]);
            buf[ptid] = a;
            buf[ptid + HALF] = b;
            buf[ptid + 2 * HALF] = c;
            buf[ptid + 3 * HALF] = d;

            float m0 = fmaxf(fmaxf(a.x, a.y), fmaxf(a.z, a.w));
            float m1 = fmaxf(fmaxf(b.x, b.y), fmaxf(b.z, b.w));
            float m2 = fmaxf(fmaxf(c.x, c.y), fmaxf(c.z, c.w));
            float m3 = fmaxf(fmaxf(d.x, d.y), fmaxf(d.z, d.w));
            float m = fmaxf(fmaxf(m0, m1), fmaxf(m2, m3));
            #pragma unroll
            for (int off = 16; off; off >>= 1)
                m = fmaxf(m, __shfl_xor_sync(0xFFFFFFFFu, m, off));
            if ((ptid & 31) == 0) s_red[st][pwid] = m;

            asm volatile("bar.sync 1, %0;" :: "n"(HALF) : "memory");  // drains STS

            if (ptid == 0) {
                float v = s_red[st][0];
                #pragma unroll
                for (int r = 1; r < HALF / 32; r++) v = fmaxf(v, s_red[st][r]);
                const int sample = w >> 5;
                atomicMax(&g_smax[sample], ord_encode(v));
                __threadfence();
                atomicAdd(&g_arrive[sample], 1u);
                st_release_sh(&s_state[st], 1);   // stage full
            }
            st = (st + 1 == NSTAGES) ? 0 : st + 1;
        }
    } else {
        // ================= CONSUMERS (warps 16-31) =================
        const int ctid = tid - HALF;
        int st = 0;
        for (int w = bid; w < TOTAL_WORK; w += GRID) {
            while (ld_acquire_sh(&s_state[st]) != 1) __nanosleep(40);

            const int sample = w >> 5;
            if (ctid == 0) {
                while (ld_acquire_gpu(&g_arrive[sample]) < CHUNKS)
                    __nanosleep(40);
                __threadfence();
                float mx = ord_decode(g_smax[sample]);
                float sm = softplus_accurate(mx);   // = max(softplus(x))
                s_scale[st] = (sm > EPS) ? (1.0f / sm) : 1.0f;
            }
            asm volatile("bar.sync 2, %0;" :: "n"(HALF) : "memory");  // scale ready

            const float scale = s_scale[st];
            const float scale_ln2 = scale * LN2;
            const float4* buf = ring + st * CHUNK_N4;
            float4* __restrict__ o =
                reinterpret_cast<float4*>(out) + (size_t)w * CHUNK_N4;

            #pragma unroll
            for (int i = 0; i < 4; i++) {
                float4 v = buf[i * HALF + ctid];
                float4 r;
                r.x = softplus_scaled(v.x, scale, scale_ln2);
                r.y = softplus_scaled(v.y, scale, scale_ln2);
                r.z = softplus_scaled(v.z, scale, scale_ln2);
                r.w = softplus_scaled(v.w, scale, scale_ln2);
                __stcs(&o[i * HALF + ctid], r);
            }

            asm volatile("bar.sync 2, %0;" :: "n"(HALF) : "memory");  // all read buf

            if (ctid == 0) {
                unsigned old = atomicAdd(&g_leave[sample], 1u);
                if (old == CHUNKS - 1) {          // last chunk resets the sample
                    g_smax[sample] = 0u;
                    g_arrive[sample] = 0u;
                    __threadfence();
                    g_leave[sample] = 0u;
                }
                st_release_sh(&s_state[st], 0);   // stage empty
            }
            st = (st + 1 == NSTAGES) ? 0 : st + 1;
        }
    }
}

extern "C" void kernel_launch(void* const* d_in, const int* in_sizes, int n_in,
                              void* d_out, int out_size) {
    const float* x = (const float*)d_in[0];
    float* out = (float*)d_out;
    static bool attr_set = false;
    if (!attr_set) {
        cudaFuncSetAttribute(ws_kernel,
                             cudaFuncAttributeMaxDynamicSharedMemorySize,
                             SMEM_BYTES);
        attr_set = true;
    }
    ws_kernel<<<GRID, THREADS, SMEM_BYTES>>>(x, out);
}

// round 15
// speedup vs baseline: 1.1661x; 1.1661x over previous
#include <cuda_runtime.h>
#include <cstdint>
#include <math.h>

// x [128, 1, 512, 512] fp32.
//   pred = softplus(x); m = max over sample; out = (m > 1e-8) ? pred/m : pred.
// softplus monotone => m = softplus(max(x)).
//
// R15: bulk designs are capped at 57.6us by ~7.3 TB/s of LTS bandwidth over
// 402 MB (read + L2 re-read + write). SMEM staging failed 3x on structure.
// This version routes the re-read through L1 (free of LTS): persistent grid,
// per round each CTA (a) issues pass-1 loads for chunk w (default policy ->
// L1), (b) runs pass-2 on chunk w-2*GRID (same SM, L1-hit; its sample's max
// was published two rounds ago so the spin never blocks; the pass-1 loads
// remain in flight underneath), (c) reduces + publishes the pass-1 max.
// L1 live set: 4 CTAs/SM * 3 chunks * 16 KB = 192 KB <= 228 KB L1D.
// Counters self-reset via leave counter (proven across R12-R14 replays).

#define SAMPLES 128
#define SAMPLE_ELEMS (512 * 512)            // 262144
#define CHUNKS 64                           // chunks per sample
#define CHUNK_N4 (SAMPLE_ELEMS / CHUNKS / 4)  // 1024 float4 = 16 KB
#define THREADS 256                         // 4 float4 per thread
#define NWARPS (THREADS / 32)               // 8
#define GRID 592                            // 148 SMs * 4 CTAs
#define DEPTH 2                             // pipeline depth (rounds)
#define TOTAL_WORK (SAMPLES * CHUNKS)       // 8192
#define EPS 1e-8f
#define LOG2E 1.4426950408889634f
#define LN2   0.6931471805599453f

__device__ unsigned g_smax[SAMPLES];        // ordered-uint max; 0 = empty
__device__ unsigned g_arrive[SAMPLES];
__device__ unsigned g_leave[SAMPLES];       // self-reset for graph replay

__device__ __forceinline__ unsigned ord_encode(float f) {
    unsigned u = __float_as_uint(f);
    return (u >> 31) ? ~u : (u | 0x80000000u);
}
__device__ __forceinline__ float ord_decode(unsigned u) {
    return __uint_as_float((u >> 31) ? (u ^ 0x80000000u) : ~u);
}
__device__ __forceinline__ float softplus_accurate(float x) {
    return fmaxf(x, 0.0f) + log1pf(__expf(-fabsf(x)));
}
__device__ __forceinline__ float ex2f(float x) {
    float r; asm("ex2.approx.ftz.f32 %0, %1;" : "=f"(r) : "f"(x)); return r;
}
__device__ __forceinline__ float lg2f(float x) {
    float r; asm("lg2.approx.ftz.f32 %0, %1;" : "=f"(r) : "f"(x)); return r;
}
__device__ __forceinline__ float softplus_scaled(float x, float scale, float scale_ln2) {
    float t = ex2f(-LOG2E * fabsf(x));      // e^(-|x|)
    float l = lg2f(1.0f + t);               // log2(1 + e^-|x|)
    return fmaf(scale, fmaxf(x, 0.0f), scale_ln2 * l);
}
__device__ __forceinline__ unsigned ld_acquire_gpu(const unsigned* p) {
    unsigned v;
    asm volatile("ld.acquire.gpu.u32 %0, [%1];" : "=r"(v) : "l"(p));
    return v;
}

__global__ __launch_bounds__(THREADS, 4)
void l1pipe_kernel(const float* __restrict__ x, float* __restrict__ out) {
    __shared__ float s_red[NWARPS];
    __shared__ float s_scale;

    const int tid = threadIdx.x;
    const int bid = blockIdx.x;

    for (int r = 0;; r++) {
        const int w1 = bid + r * GRID;              // pass-1 chunk
        const int w2 = w1 - DEPTH * GRID;           // pass-2 chunk (2 rounds old)
        if (w2 >= TOTAL_WORK) break;
        const bool do1 = (w1 < TOTAL_WORK);
        const bool do2 = (w2 >= 0);

        // ---- (a) Issue pass-1 loads (default policy: fill L1 + L2) ----
        float4 a, b, c, d;
        if (do1) {
            const float4* __restrict__ xin =
                reinterpret_cast<const float4*>(x) + (size_t)w1 * CHUNK_N4;
            a = xin[tid];
            b = xin[tid + THREADS];
            c = xin[tid + 2 * THREADS];
            d = xin[tid + 3 * THREADS];
        }

        // ---- (b) Pass 2 on w2 while pass-1 loads are in flight ----
        if (do2) {
            const int sample = w2 >> 6;             // / CHUNKS
            if (tid == 0) {
                while (ld_acquire_gpu(&g_arrive[sample]) < CHUNKS)
                    __nanosleep(32);                // ~never blocks at DEPTH=2
                __threadfence();
                float mx = ord_decode(g_smax[sample]);
                float sm = softplus_accurate(mx);   // = max(softplus(x))
                s_scale = (sm > EPS) ? (1.0f / sm) : 1.0f;
            }
            __syncthreads();
            const float scale = s_scale;
            const float scale_ln2 = scale * LN2;

            const size_t off4 = (size_t)w2 * CHUNK_N4;
            const float4* __restrict__ xin2 =
                reinterpret_cast<const float4*>(x) + off4;
            float4* __restrict__ o = reinterpret_cast<float4*>(out) + off4;

            // Re-read: L1 hits (loaded 2 rounds ago on this SM). __ldcs marks
            // the lines evict-first, freeing L1 for the incoming rounds.
            float4 p = __ldcs(&xin2[tid]);
            float4 q = __ldcs(&xin2[tid + THREADS]);
            float4 s = __ldcs(&xin2[tid + 2 * THREADS]);
            float4 t = __ldcs(&xin2[tid + 3 * THREADS]);
            float4 rp, rq, rs, rt;
            rp.x = softplus_scaled(p.x, scale, scale_ln2);
            rp.y = softplus_scaled(p.y, scale, scale_ln2);
            rp.z = softplus_scaled(p.z, scale, scale_ln2);
            rp.w = softplus_scaled(p.w, scale, scale_ln2);
            rq.x = softplus_scaled(q.x, scale, scale_ln2);
            rq.y = softplus_scaled(q.y, scale, scale_ln2);
            rq.z = softplus_scaled(q.z, scale, scale_ln2);
            rq.w = softplus_scaled(q.w, scale, scale_ln2);
            rs.x = softplus_scaled(s.x, scale, scale_ln2);
            rs.y = softplus_scaled(s.y, scale, scale_ln2);
            rs.z = softplus_scaled(s.z, scale, scale_ln2);
            rs.w = softplus_scaled(s.w, scale, scale_ln2);
            rt.x = softplus_scaled(t.x, scale, scale_ln2);
            rt.y = softplus_scaled(t.y, scale, scale_ln2);
            rt.z = softplus_scaled(t.z, scale, scale_ln2);
            rt.w = softplus_scaled(t.w, scale, scale_ln2);
            __stcs(&o[tid], rp);
            __stcs(&o[tid + THREADS], rq);
            __stcs(&o[tid + 2 * THREADS], rs);
            __stcs(&o[tid + 3 * THREADS], rt);
        }

        // ---- (c) Reduce pass-1 max, publish arrival ----
        if (do1) {
            float m0 = fmaxf(fmaxf(a.x, a.y), fmaxf(a.z, a.w));
            float m1 = fmaxf(fmaxf(b.x, b.y), fmaxf(b.z, b.w));
            float m2 = fmaxf(fmaxf(c.x, c.y), fmaxf(c.z, c.w));
            float m3 = fmaxf(fmaxf(d.x, d.y), fmaxf(d.z, d.w));
            float m = fmaxf(fmaxf(m0, m1), fmaxf(m2, m3));
            #pragma unroll
            for (int off = 16; off; off >>= 1)
                m = fmaxf(m, __shfl_xor_sync(0xFFFFFFFFu, m, off));
            if ((tid & 31) == 0) s_red[tid >> 5] = m;
            __syncthreads();
            if (tid < 32) {
                float v = (tid < NWARPS) ? s_red[tid] : -INFINITY;
                #pragma unroll
                for (int off = NWARPS / 2; off; off >>= 1)
                    v = fmaxf(v, __shfl_xor_sync(0xFFFFFFFFu, v, off));
                if (tid == 0) {
                    const int sample = w1 >> 6;
                    atomicMax(&g_smax[sample], ord_encode(v));
                    __threadfence();
                    atomicAdd(&g_arrive[sample], 1u);
                }
            }
        }

        // ---- (d) Leave / self-reset for w2's sample ----
        if (do2 && tid == 0) {
            const int sample = w2 >> 6;
            unsigned old = atomicAdd(&g_leave[sample], 1u);
            if (old == CHUNKS - 1) {                // last chunk out resets
                g_smax[sample] = 0u;
                g_arrive[sample] = 0u;
                __threadfence();
                g_leave[sample] = 0u;
            }
        }
        __syncthreads();                            // s_red / s_scale reuse guard
    }
}

extern "C" void kernel_launch(void* const* d_in, const int* in_sizes, int n_in,
                              void* d_out, int out_size) {
    const float* x = (const float*)d_in[0];
    float* out = (float*)d_out;
    l1pipe_kernel<<<GRID, THREADS>>>(x, out);
}

// round 16
// speedup vs baseline: 1.7652x; 1.5138x over previous
#include <cuda_runtime.h>
#include <cstdint>
#include <math.h>

// x [128, 1, 512, 512] fp32.
//   pred = softplus(x); m = max over sample; out = (m > 1e-8) ? pred/m : pred.
// softplus monotone => m = softplus(max(x)).
//
// R16 = R8 bulk structure (best: 57.6us) + Programmatic Dependent Launch.
// R12-R15 proved in-kernel cross-CTA waits cost more than the L2 traffic they
// save. Instead, overlap KERNEL BOUNDARIES: every kernel fires
// launch_dependents at entry; norm_kernel issues its first loads BEFORE
// griddepcontrol.wait (only the partial-max read needs the dependency);
// max_kernel has no data dependency on the preceding norm_kernel and skips
// the wait entirely. 4 slices of 32 samples keep K2 reads L2-resident.

#define SAMPLES 128
#define SLICES 4
#define SAMPLES_PER_SLICE (SAMPLES / SLICES)       // 32
#define SAMPLE_ELEMS (512 * 512)                   // 262144
#define SAMPLE_N4 (SAMPLE_ELEMS / 4)               // 65536 float4
#define CHUNKS 32                                  // CTAs per sample
#define CHUNK_N4 (SAMPLE_N4 / CHUNKS)              // 2048 float4 per CTA
#define SLICE_BLOCKS (SAMPLES_PER_SLICE * CHUNKS)  // 1024
#define THREADS 256                                // 8 float4 per thread
#define EPS 1e-8f
#define LOG2E 1.4426950408889634f
#define LN2   0.6931471805599453f

__device__ float g_partial[SAMPLES * CHUNKS];      // disjoint slots per slice

__device__ __forceinline__ float softplus_accurate(float x) {
    return fmaxf(x, 0.0f) + log1pf(__expf(-fabsf(x)));
}
__device__ __forceinline__ float ex2f(float x) {
    float r; asm("ex2.approx.ftz.f32 %0, %1;" : "=f"(r) : "f"(x)); return r;
}
__device__ __forceinline__ float lg2f(float x) {
    float r; asm("lg2.approx.ftz.f32 %0, %1;" : "=f"(r) : "f"(x)); return r;
}
__device__ __forceinline__ float softplus_scaled(float x, float scale, float scale_ln2) {
    float t = ex2f(-LOG2E * fabsf(x));             // e^(-|x|)
    float l = lg2f(1.0f + t);                      // log2(1 + e^-|x|)
    return fmaf(scale, fmaxf(x, 0.0f), scale_ln2 * l);
}

// ---------- K1: per-chunk max over one slice (no wait needed) ----------
__global__ __launch_bounds__(THREADS)
void max_kernel(const float* __restrict__ x_slice, float* __restrict__ partial_slice) {
    // Let the next kernel start occupying SMs as we drain.
    asm volatile("griddepcontrol.launch_dependents;");

    const float4* __restrict__ xin =
        reinterpret_cast<const float4*>(x_slice) + (size_t)blockIdx.x * CHUNK_N4;
    const int tid = threadIdx.x;

    float m0 = -INFINITY, m1 = -INFINITY, m2 = -INFINITY, m3 = -INFINITY;
    #pragma unroll
    for (int it = 0; it < 2; it++) {
        int base = it * 4 * THREADS + tid;
        float4 a = xin[base];
        float4 b = xin[base + THREADS];
        float4 c = xin[base + 2 * THREADS];
        float4 d = xin[base + 3 * THREADS];
        m0 = fmaxf(m0, fmaxf(fmaxf(a.x, a.y), fmaxf(a.z, a.w)));
        m1 = fmaxf(m1, fmaxf(fmaxf(b.x, b.y), fmaxf(b.z, b.w)));
        m2 = fmaxf(m2, fmaxf(fmaxf(c.x, c.y), fmaxf(c.z, c.w)));
        m3 = fmaxf(m3, fmaxf(fmaxf(d.x, d.y), fmaxf(d.z, d.w)));
    }
    float m = fmaxf(fmaxf(m0, m1), fmaxf(m2, m3));

    #pragma unroll
    for (int off = 16; off; off >>= 1)
        m = fmaxf(m, __shfl_xor_sync(0xFFFFFFFFu, m, off));

    __shared__ float red[THREADS / 32];
    if ((tid & 31) == 0) red[tid >> 5] = m;
    __syncthreads();
    if (tid < (THREADS / 32)) {
        float v = red[tid];
        #pragma unroll
        for (int off = (THREADS / 64); off; off >>= 1)
            v = fmaxf(v, __shfl_xor_sync(0xFFFFFFFFu, v, off));
        if (tid == 0) partial_slice[blockIdx.x] = v;   // distinct slot, no atomic
    }
}

// ---------- K2: loads first, wait, then reduce partials + normalize ----------
__global__ __launch_bounds__(THREADS)
void norm_kernel(const float* __restrict__ x_slice, float* __restrict__ out_slice,
                 const float* __restrict__ partial_slice) {
    asm volatile("griddepcontrol.launch_dependents;");

    const int sample = blockIdx.x >> 5;              // / CHUNKS (within slice)
    const size_t off4 = (size_t)blockIdx.x * CHUNK_N4;
    const float4* __restrict__ xin = reinterpret_cast<const float4*>(x_slice) + off4;
    float4* __restrict__ o = reinterpret_cast<float4*>(out_slice) + off4;
    const int tid = threadIdx.x;

    // Issue first batch of loads BEFORE waiting on K1 (no dependency on it).
    float4 a0 = __ldcs(&xin[tid]);
    float4 b0 = __ldcs(&xin[tid + THREADS]);
    float4 c0 = __ldcs(&xin[tid + 2 * THREADS]);
    float4 d0 = __ldcs(&xin[tid + 3 * THREADS]);

    // Now require the preceding max_kernel to be complete (partials visible).
    asm volatile("griddepcontrol.wait;" ::: "memory");

    __shared__ float s_scale;
    if (tid < 32) {
        float v = partial_slice[sample * CHUNKS + tid];  // CHUNKS == 32
        #pragma unroll
        for (int off = 16; off; off >>= 1)
            v = fmaxf(v, __shfl_xor_sync(0xFFFFFFFFu, v, off));
        if (tid == 0) {
            float sm = softplus_accurate(v);   // = max(softplus(x)), monotone
            s_scale = (sm > EPS) ? (1.0f / sm) : 1.0f;
        }
    }
    __syncthreads();
    const float scale = s_scale;
    const float scale_ln2 = scale * LN2;

    // Batch 1 (loads already in flight / done).
    {
        float4 ra, rb, rc, rd;
        ra.x = softplus_scaled(a0.x, scale, scale_ln2);
        ra.y = softplus_scaled(a0.y, scale, scale_ln2);
        ra.z = softplus_scaled(a0.z, scale, scale_ln2);
        ra.w = softplus_scaled(a0.w, scale, scale_ln2);
        rb.x = softplus_scaled(b0.x, scale, scale_ln2);
        rb.y = softplus_scaled(b0.y, scale, scale_ln2);
        rb.z = softplus_scaled(b0.z, scale, scale_ln2);
        rb.w = softplus_scaled(b0.w, scale, scale_ln2);
        rc.x = softplus_scaled(c0.x, scale, scale_ln2);
        rc.y = softplus_scaled(c0.y, scale, scale_ln2);
        rc.z = softplus_scaled(c0.z, scale, scale_ln2);
        rc.w = softplus_scaled(c0.w, scale, scale_ln2);
        rd.x = softplus_scaled(d0.x, scale, scale_ln2);
        rd.y = softplus_scaled(d0.y, scale, scale_ln2);
        rd.z = softplus_scaled(d0.z, scale, scale_ln2);
        rd.w = softplus_scaled(d0.w, scale, scale_ln2);
        __stcs(&o[tid], ra);
        __stcs(&o[tid + THREADS], rb);
        __stcs(&o[tid + 2 * THREADS], rc);
        __stcs(&o[tid + 3 * THREADS], rd);
    }
    // Batch 2.
    {
        int base = 4 * THREADS + tid;
        float4 a = __ldcs(&xin[base]);
        float4 b = __ldcs(&xin[base + THREADS]);
        float4 c = __ldcs(&xin[base + 2 * THREADS]);
        float4 d = __ldcs(&xin[base + 3 * THREADS]);
        float4 ra, rb, rc, rd;
        ra.x = softplus_scaled(a.x, scale, scale_ln2);
        ra.y = softplus_scaled(a.y, scale, scale_ln2);
        ra.z = softplus_scaled(a.z, scale, scale_ln2);
        ra.w = softplus_scaled(a.w, scale, scale_ln2);
        rb.x = softplus_scaled(b.x, scale, scale_ln2);
        rb.y = softplus_scaled(b.y, scale, scale_ln2);
        rb.z = softplus_scaled(b.z, scale, scale_ln2);
        rb.w = softplus_scaled(b.w, scale, scale_ln2);
        rc.x = softplus_scaled(c.x, scale, scale_ln2);
        rc.y = softplus_scaled(c.y, scale, scale_ln2);
        rc.z = softplus_scaled(c.z, scale, scale_ln2);
        rc.w = softplus_scaled(c.w, scale, scale_ln2);
        rd.x = softplus_scaled(d.x, scale, scale_ln2);
        rd.y = softplus_scaled(d.y, scale, scale_ln2);
        rd.z = softplus_scaled(d.z, scale, scale_ln2);
        rd.w = softplus_scaled(d.w, scale, scale_ln2);
        __stcs(&o[base], ra);
        __stcs(&o[base + THREADS], rb);
        __stcs(&o[base + 2 * THREADS], rc);
        __stcs(&o[base + 3 * THREADS], rd);
    }
}

extern "C" void kernel_launch(void* const* d_in, const int* in_sizes, int n_in,
                              void* d_out, int out_size) {
    const float* x = (const float*)d_in[0];
    float* out = (float*)d_out;

    float* gp = nullptr;
    cudaGetSymbolAddress((void**)&gp, g_partial);

    cudaLaunchAttribute attr[1];
    attr[0].id = cudaLaunchAttributeProgrammaticStreamSerialization;
    attr[0].val.programmaticStreamSerializationAllowed = 1;

    cudaLaunchConfig_t cfg = {};
    cfg.gridDim = dim3(SLICE_BLOCKS);
    cfg.blockDim = dim3(THREADS);
    cfg.dynamicSmemBytes = 0;
    cfg.stream = 0;                      // legacy default stream (captured)
    cfg.attrs = attr;
    cfg.numAttrs = 1;

    const size_t se = (size_t)SAMPLES_PER_SLICE * SAMPLE_ELEMS;
    for (int s = 0; s < SLICES; s++) {
        const float* xs = x + s * se;
        float* os = out + s * se;
        float* ps = gp + s * SLICE_BLOCKS;
        cudaLaunchKernelEx(&cfg, max_kernel, xs, ps);
        cudaLaunchKernelEx(&cfg, norm_kernel, xs, os, (const float*)ps);
    }
}